// round 12
// baseline (speedup 1.0000x reference)
#include <cuda_runtime.h>

// SemiLoss: masked mean over gathered columns of
//   bce + (o-sharp)^2 + (oc-sharp)^2
// sharp = o>0.5 ? o + (1-o)/4 : o - o/4  = 0.75*o + (o>0.5 ? 0.25 : 0)
// bce   = -( y*max(log(o),-100) + (1-y)*max(log(1-o),-100) )

#define LOG_CLAMP -100.0f

// Scratch accumulators (no device allocation allowed).
__device__ double g_total;
__device__ unsigned long long g_rows;

__global__ void sl_init_kernel() {
    g_total = 0.0;
    g_rows = 0ull;
}

__device__ __forceinline__ float sl_elem(float o, float oc, float y) {
    float sharp = 0.75f * o + (o > 0.5f ? 0.25f : 0.0f);
    float lo  = fmaxf(__logf(o), LOG_CLAMP);
    float l1  = fmaxf(__logf(1.0f - o), LOG_CLAMP);
    float bce = -(y * lo + (1.0f - y) * l1);
    float d1 = o - sharp;
    float d2 = oc - sharp;
    return bce + d1 * d1 + d2 * d2;
}

__global__ __launch_bounds__(256)
void semi_loss_kernel(const float* __restrict__ out_p,
                      const float* __restrict__ oc_p,
                      const float* __restrict__ y_p,
                      const long long* __restrict__ cidx,
                      const unsigned char* __restrict__ mask,
                      int B, int C, int K)
{
    __shared__ int s_idx[128];  // K <= 128
    int tid = threadIdx.x;
    if (tid < K) s_idx[tid] = (int)cidx[tid];
    __syncthreads();

    const int lane = tid & 31;
    const int wid  = tid >> 5;

    long long row = (long long)blockIdx.x * 8 + wid;  // one warp per row

    float acc = 0.0f;
    int active = 0;

    if (row < B && mask[row]) {
        active = 1;
        const size_t base = (size_t)row * (size_t)C;
        const float* ro = out_p + base;
        const float* rc = oc_p  + base;
        const float* ry = y_p   + base;

        // lane handles columns lane, lane+32, ... (K=64 -> 2 iters)
        #pragma unroll 2
        for (int k = lane; k < K; k += 32) {
            int ci = s_idx[k];
            float o  = __ldg(ro + ci);
            float oc = __ldg(rc + ci);
            float y  = __ldg(ry + ci);
            acc += sl_elem(o, oc, y);
        }
    }

    // warp reduce
    #pragma unroll
    for (int off = 16; off > 0; off >>= 1)
        acc += __shfl_down_sync(0xffffffffu, acc, off);

    __shared__ float s_acc[8];
    __shared__ int   s_cnt[8];
    if (lane == 0) {
        s_acc[wid] = acc;
        s_cnt[wid] = active;
    }
    __syncthreads();

    if (wid == 0) {
        float v = (lane < 8) ? s_acc[lane] : 0.0f;
        int   c = (lane < 8) ? s_cnt[lane] : 0;
        #pragma unroll
        for (int off = 4; off > 0; off >>= 1) {
            v += __shfl_down_sync(0xffffffffu, v, off);
            c += __shfl_down_sync(0xffffffffu, c, off);
        }
        if (lane == 0) {
            if (v != 0.0f) atomicAdd(&g_total, (double)v);
            if (c)         atomicAdd(&g_rows, (unsigned long long)c);
        }
    }
}

__global__ void sl_finalize_kernel(float* __restrict__ out, int K) {
    double cnt = (double)g_rows * (double)K;
    out[0] = (float)(g_total / cnt);
}

extern "C" void kernel_launch(void* const* d_in, const int* in_sizes, int n_in,
                              void* d_out, int out_size)
{
    const float*         o    = (const float*)d_in[0];
    const float*         oc   = (const float*)d_in[1];
    const float*         y    = (const float*)d_in[2];
    const long long*     cidx = (const long long*)d_in[3];
    const unsigned char* mask = (const unsigned char*)d_in[4];

    const int B = in_sizes[4];               // batch_mask length
    const int C = in_sizes[0] / B;           // columns
    const int K = in_sizes[3];               // gathered columns

    sl_init_kernel<<<1, 1>>>();

    const int warpsPerBlock = 8;
    const int blocks = (B + warpsPerBlock - 1) / warpsPerBlock;
    semi_loss_kernel<<<blocks, 256>>>(o, oc, y, cidx, mask, B, C, K);

    sl_finalize_kernel<<<1, 1>>>((float*)d_out, K);
}

// round 13
// speedup vs baseline: 1.0315x; 1.0315x over previous
#include <cuda_runtime.h>

// SemiLoss: masked mean over gathered columns of
//   bce + (o-sharp)^2 + (oc-sharp)^2
// sharp = o>0.5 ? o + (1-o)/4 : o - o/4  = 0.75*o + (o>0.5 ? 0.25 : 0)
// bce   = -( y*max(log(o),-100) + (1-y)*max(log(1-o),-100) )

#define LOG_CLAMP -100.0f

// Scratch accumulators (no device allocation allowed).
__device__ double g_total;
__device__ unsigned long long g_rows;

__global__ void sl_init_kernel() {
    g_total = 0.0;
    g_rows = 0ull;
}

__device__ __forceinline__ float sl_elem(float o, float oc, float y) {
    float sharp = 0.75f * o + (o > 0.5f ? 0.25f : 0.0f);
    float lo  = fmaxf(__logf(o), LOG_CLAMP);
    float l1  = fmaxf(__logf(1.0f - o), LOG_CLAMP);
    float bce = -(y * lo + (1.0f - y) * l1);
    float d1 = o - sharp;
    float d2 = oc - sharp;
    return bce + d1 * d1 + d2 * d2;
}

__global__ __launch_bounds__(256)
void semi_loss_kernel(const float* __restrict__ out_p,
                      const float* __restrict__ oc_p,
                      const float* __restrict__ y_p,
                      const long long* __restrict__ cidx,
                      const unsigned char* __restrict__ mask,
                      int B, int C, int K)
{
    __shared__ int s_idx[128];  // K <= 128
    int tid = threadIdx.x;
    if (tid < K) s_idx[tid] = (int)cidx[tid];
    __syncthreads();

    const int lane = tid & 31;
    const int wid  = tid >> 5;

    long long row = (long long)blockIdx.x * 8 + wid;  // one warp per row

    float acc = 0.0f;
    int active = 0;

    if (row < B && mask[row]) {
        active = 1;
        const size_t base = (size_t)row * (size_t)C;
        const float* ro = out_p + base;
        const float* rc = oc_p  + base;
        const float* ry = y_p   + base;

        // lane handles columns lane, lane+32, ... (K=64 -> 2 iters)
        #pragma unroll 2
        for (int k = lane; k < K; k += 32) {
            int ci = s_idx[k];
            float o  = __ldg(ro + ci);
            float oc = __ldg(rc + ci);
            float y  = __ldg(ry + ci);
            acc += sl_elem(o, oc, y);
        }
    }

    // warp reduce
    #pragma unroll
    for (int off = 16; off > 0; off >>= 1)
        acc += __shfl_down_sync(0xffffffffu, acc, off);

    __shared__ float s_acc[8];
    __shared__ int   s_cnt[8];
    if (lane == 0) {
        s_acc[wid] = acc;
        s_cnt[wid] = active;
    }
    __syncthreads();

    if (wid == 0) {
        float v = (lane < 8) ? s_acc[lane] : 0.0f;
        int   c = (lane < 8) ? s_cnt[lane] : 0;
        #pragma unroll
        for (int off = 4; off > 0; off >>= 1) {
            v += __shfl_down_sync(0xffffffffu, v, off);
            c += __shfl_down_sync(0xffffffffu, c, off);
        }
        if (lane == 0) {
            if (v != 0.0f) atomicAdd(&g_total, (double)v);
            if (c)         atomicAdd(&g_rows, (unsigned long long)c);
        }
    }
}

__global__ void sl_finalize_kernel(float* __restrict__ out, int K) {
    double cnt = (double)g_rows * (double)K;
    out[0] = (float)(g_total / cnt);
}

extern "C" void kernel_launch(void* const* d_in, const int* in_sizes, int n_in,
                              void* d_out, int out_size)
{
    const float*         o    = (const float*)d_in[0];
    const float*         oc   = (const float*)d_in[1];
    const float*         y    = (const float*)d_in[2];
    const long long*     cidx = (const long long*)d_in[3];
    const unsigned char* mask = (const unsigned char*)d_in[4];

    const int B = in_sizes[4];               // batch_mask length
    const int C = in_sizes[0] / B;           // columns
    const int K = in_sizes[3];               // gathered columns

    sl_init_kernel<<<1, 1>>>();

    const int warpsPerBlock = 8;
    const int blocks = (B + warpsPerBlock - 1) / warpsPerBlock;
    semi_loss_kernel<<<blocks, 256>>>(o, oc, y, cidx, mask, B, C, K);

    sl_finalize_kernel<<<1, 1>>>((float*)d_out, K);
}

// round 14
// speedup vs baseline: 1.0436x; 1.0118x over previous
#include <cuda_runtime.h>

// SemiLoss: masked mean over gathered columns of
//   bce + (o-sharp)^2 + (oc-sharp)^2
// sharp = o>0.5 ? o + (1-o)/4 : o - o/4  = 0.75*o + (o>0.5 ? 0.25 : 0)
// bce   = -( y*max(log(o),-100) + (1-y)*max(log(1-o),-100) )

#define LOG_CLAMP -100.0f

// Scratch accumulators (no device allocation allowed).
__device__ double g_total;
__device__ unsigned long long g_rows;

__global__ void sl_init_kernel() {
    g_total = 0.0;
    g_rows = 0ull;
}

__device__ __forceinline__ float sl_elem(float o, float oc, float y) {
    float sharp = 0.75f * o + (o > 0.5f ? 0.25f : 0.0f);
    float lo  = fmaxf(__logf(o), LOG_CLAMP);
    float l1  = fmaxf(__logf(1.0f - o), LOG_CLAMP);
    float bce = -(y * lo + (1.0f - y) * l1);
    float d1 = o - sharp;
    float d2 = oc - sharp;
    return bce + d1 * d1 + d2 * d2;
}

__global__ __launch_bounds__(256)
void semi_loss_kernel(const float* __restrict__ out_p,
                      const float* __restrict__ oc_p,
                      const float* __restrict__ y_p,
                      const long long* __restrict__ cidx,
                      const unsigned char* __restrict__ mask,
                      int B, int C, int K)
{
    __shared__ int s_idx[128];  // K <= 128
    int tid = threadIdx.x;
    if (tid < K) s_idx[tid] = (int)cidx[tid];
    __syncthreads();

    const int lane = tid & 31;
    const int wid  = tid >> 5;

    long long row = (long long)blockIdx.x * 8 + wid;  // one warp per row

    float acc = 0.0f;
    int active = 0;

    if (row < B && mask[row]) {
        active = 1;
        const size_t base = (size_t)row * (size_t)C;
        const float* ro = out_p + base;
        const float* rc = oc_p  + base;
        const float* ry = y_p   + base;

        // lane handles columns lane, lane+32, ... (K=64 -> 2 iters)
        #pragma unroll 2
        for (int k = lane; k < K; k += 32) {
            int ci = s_idx[k];
            float o  = __ldg(ro + ci);
            float oc = __ldg(rc + ci);
            float y  = __ldg(ry + ci);
            acc += sl_elem(o, oc, y);
        }
    }

    // warp reduce
    #pragma unroll
    for (int off = 16; off > 0; off >>= 1)
        acc += __shfl_down_sync(0xffffffffu, acc, off);

    __shared__ float s_acc[8];
    __shared__ int   s_cnt[8];
    if (lane == 0) {
        s_acc[wid] = acc;
        s_cnt[wid] = active;
    }
    __syncthreads();

    if (wid == 0) {
        float v = (lane < 8) ? s_acc[lane] : 0.0f;
        int   c = (lane < 8) ? s_cnt[lane] : 0;
        #pragma unroll
        for (int off = 4; off > 0; off >>= 1) {
            v += __shfl_down_sync(0xffffffffu, v, off);
            c += __shfl_down_sync(0xffffffffu, c, off);
        }
        if (lane == 0) {
            if (v != 0.0f) atomicAdd(&g_total, (double)v);
            if (c)         atomicAdd(&g_rows, (unsigned long long)c);
        }
    }
}

__global__ void sl_finalize_kernel(float* __restrict__ out, int K) {
    double cnt = (double)g_rows * (double)K;
    out[0] = (float)(g_total / cnt);
}

extern "C" void kernel_launch(void* const* d_in, const int* in_sizes, int n_in,
                              void* d_out, int out_size)
{
    const float*         o    = (const float*)d_in[0];
    const float*         oc   = (const float*)d_in[1];
    const float*         y    = (const float*)d_in[2];
    const long long*     cidx = (const long long*)d_in[3];
    const unsigned char* mask = (const unsigned char*)d_in[4];

    const int B = in_sizes[4];               // batch_mask length
    const int C = in_sizes[0] / B;           // columns
    const int K = in_sizes[3];               // gathered columns

    sl_init_kernel<<<1, 1>>>();

    const int warpsPerBlock = 8;
    const int blocks = (B + warpsPerBlock - 1) / warpsPerBlock;
    semi_loss_kernel<<<blocks, 256>>>(o, oc, y, cidx, mask, B, C, K);

    sl_finalize_kernel<<<1, 1>>>((float*)d_out, K);
}

// round 15
// speedup vs baseline: 1.0449x; 1.0012x over previous
#include <cuda_runtime.h>

// SemiLoss: masked mean over gathered columns of
//   bce + (o-sharp)^2 + (oc-sharp)^2
// sharp = o>0.5 ? o + (1-o)/4 : o - o/4  = 0.75*o + (o>0.5 ? 0.25 : 0)
// bce   = -( y*max(log(o),-100) + (1-y)*max(log(1-o),-100) )

#define LOG_CLAMP -100.0f

// Scratch accumulators (no device allocation allowed).
__device__ double g_total;
__device__ unsigned long long g_rows;

__global__ void sl_init_kernel() {
    g_total = 0.0;
    g_rows = 0ull;
}

__device__ __forceinline__ float sl_elem(float o, float oc, float y) {
    float sharp = 0.75f * o + (o > 0.5f ? 0.25f : 0.0f);
    float lo  = fmaxf(__logf(o), LOG_CLAMP);
    float l1  = fmaxf(__logf(1.0f - o), LOG_CLAMP);
    float bce = -(y * lo + (1.0f - y) * l1);
    float d1 = o - sharp;
    float d2 = oc - sharp;
    return bce + d1 * d1 + d2 * d2;
}

__global__ __launch_bounds__(256)
void semi_loss_kernel(const float* __restrict__ out_p,
                      const float* __restrict__ oc_p,
                      const float* __restrict__ y_p,
                      const long long* __restrict__ cidx,
                      const unsigned char* __restrict__ mask,
                      int B, int C, int K)
{
    __shared__ int s_idx[128];  // K <= 128
    int tid = threadIdx.x;
    if (tid < K) s_idx[tid] = (int)cidx[tid];
    __syncthreads();

    const int lane = tid & 31;
    const int wid  = tid >> 5;

    long long row = (long long)blockIdx.x * 8 + wid;  // one warp per row

    float acc = 0.0f;
    int active = 0;

    if (row < B && mask[row]) {
        active = 1;
        const size_t base = (size_t)row * (size_t)C;
        const float* ro = out_p + base;
        const float* rc = oc_p  + base;
        const float* ry = y_p   + base;

        // lane handles columns lane, lane+32, ... (K=64 -> 2 iters)
        #pragma unroll 2
        for (int k = lane; k < K; k += 32) {
            int ci = s_idx[k];
            float o  = __ldg(ro + ci);
            float oc = __ldg(rc + ci);
            float y  = __ldg(ry + ci);
            acc += sl_elem(o, oc, y);
        }
    }

    // warp reduce
    #pragma unroll
    for (int off = 16; off > 0; off >>= 1)
        acc += __shfl_down_sync(0xffffffffu, acc, off);

    __shared__ float s_acc[8];
    __shared__ int   s_cnt[8];
    if (lane == 0) {
        s_acc[wid] = acc;
        s_cnt[wid] = active;
    }
    __syncthreads();

    if (wid == 0) {
        float v = (lane < 8) ? s_acc[lane] : 0.0f;
        int   c = (lane < 8) ? s_cnt[lane] : 0;
        #pragma unroll
        for (int off = 4; off > 0; off >>= 1) {
            v += __shfl_down_sync(0xffffffffu, v, off);
            c += __shfl_down_sync(0xffffffffu, c, off);
        }
        if (lane == 0) {
            if (v != 0.0f) atomicAdd(&g_total, (double)v);
            if (c)         atomicAdd(&g_rows, (unsigned long long)c);
        }
    }
}

__global__ void sl_finalize_kernel(float* __restrict__ out, int K) {
    double cnt = (double)g_rows * (double)K;
    out[0] = (float)(g_total / cnt);
}

extern "C" void kernel_launch(void* const* d_in, const int* in_sizes, int n_in,
                              void* d_out, int out_size)
{
    const float*         o    = (const float*)d_in[0];
    const float*         oc   = (const float*)d_in[1];
    const float*         y    = (const float*)d_in[2];
    const long long*     cidx = (const long long*)d_in[3];
    const unsigned char* mask = (const unsigned char*)d_in[4];

    const int B = in_sizes[4];               // batch_mask length
    const int C = in_sizes[0] / B;           // columns
    const int K = in_sizes[3];               // gathered columns

    sl_init_kernel<<<1, 1>>>();

    const int warpsPerBlock = 8;
    const int blocks = (B + warpsPerBlock - 1) / warpsPerBlock;
    semi_loss_kernel<<<blocks, 256>>>(o, oc, y, cidx, mask, B, C, K);

    sl_finalize_kernel<<<1, 1>>>((float*)d_out, K);
}